// round 2
// baseline (speedup 1.0000x reference)
#include <cuda_runtime.h>

#define H     256
#define H2    128          // H/2 (float2 columns)
#define SEQL  10
#define BQ    2048
#define NTOT  327680
#define NSEG  (BQ * SEQL)  // 20480
#define NENT  20000

// ---------------- scratch (no cudaMalloc allowed) ----------------
__device__ float g_EW1[NENT * H];      // ent_embeds @ W1   (20.5 MB)
__device__ float g_A[BQ * H];          // s@W2 + r@W3 + b   (2 MB)
__device__ float g_scores[NTOT];       // per-neighbor attention score
__device__ int   g_starts[NSEG + 1];   // segment start offsets

// Packed fp32x2 FMA (Blackwell): d = a*b + c on two fp32 lanes, one instr.
__device__ __forceinline__ float2 ffma2(float2 a, float2 b, float2 c) {
    float2 d;
    asm("fma.rn.f32x2 %0, %1, %2, %3;"
        : "=l"(reinterpret_cast<unsigned long long&>(d))
        : "l"(reinterpret_cast<const unsigned long long&>(a)),
          "l"(reinterpret_cast<const unsigned long long&>(b)),
          "l"(reinterpret_cast<const unsigned long long&>(c)));
    return d;
}

__device__ __forceinline__ float tanh_fast(float x) {
    float y;
    asm("tanh.approx.f32 %0, %1;" : "=f"(y) : "f"(x));
    return y;
}

__device__ __forceinline__ float2 f2lo(float4 v) { return make_float2(v.x, v.y); }
__device__ __forceinline__ float2 f2hi(float4 v) { return make_float2(v.z, v.w); }

// ---------------------------------------------------------------------------
// Kernel 1: EW1[e,:] = ent_embeds[e] @ W1 (rows 0..255 of W).
// 128 threads; 32 entities/block (625 blocks exact). Thread = (eg, hg):
// eg = tid>>4 owns 4 entities, hg = tid&15 owns 8 float2 output columns.
// Per 2 k-steps per thread: 4 LDS.128 (duplicated act pairs) + 8 LDG.128 (W)
// + 64 FFMA2. K chunked at 128 so the duplicated smem tile is 32 KB.
// ---------------------------------------------------------------------------
#define EW_EB 32
#define EW_KC 128
__global__ void __launch_bounds__(128, 4)
ew1_kernel(const float* __restrict__ ent, const float* __restrict__ W) {
    __shared__ float2 sE[EW_EB * EW_KC];              // 32 KB, values duplicated
    const int tid   = threadIdx.x;
    const int hg    = tid & 15;                       // 16 hgroups * 8 f2 = 128
    const int eg    = tid >> 4;                       // 8 egroups * 4 ent = 32
    const int eBase = blockIdx.x * EW_EB;

    float2 acc[4][8];
#pragma unroll
    for (int e = 0; e < 4; e++)
#pragma unroll
        for (int j = 0; j < 8; j++) acc[e][j] = make_float2(0.f, 0.f);

    for (int kc = 0; kc < H; kc += EW_KC) {
        if (kc) __syncthreads();
        for (int idx = tid; idx < EW_EB * EW_KC; idx += 128) {
            const int e = idx >> 7;                   // idx / EW_KC
            const int k = idx & (EW_KC - 1);
            const float v = ent[(size_t)(eBase + e) * H + kc + k];
            sE[idx] = make_float2(v, v);
        }
        __syncthreads();

#pragma unroll 2
        for (int k = 0; k < EW_KC; k += 2) {
            const float4* wr = reinterpret_cast<const float4*>(
                                   W + (size_t)(kc + k) * H) + (hg << 2);
            const float4 w00 = wr[0],  w01 = wr[1],  w02 = wr[2],  w03 = wr[3];
            const float4 w10 = wr[64], w11 = wr[65], w12 = wr[66], w13 = wr[67];
#pragma unroll
            for (int e = 0; e < 4; e++) {
                const float4 ap = reinterpret_cast<const float4*>(sE)
                                      [((eg * 4 + e) << 6) + (k >> 1)];
                const float2 a0 = make_float2(ap.x, ap.y);   // dup(k)
                const float2 a1 = make_float2(ap.z, ap.w);   // dup(k+1)
                acc[e][0] = ffma2(a0, f2lo(w00), acc[e][0]);
                acc[e][1] = ffma2(a0, f2hi(w00), acc[e][1]);
                acc[e][2] = ffma2(a0, f2lo(w01), acc[e][2]);
                acc[e][3] = ffma2(a0, f2hi(w01), acc[e][3]);
                acc[e][4] = ffma2(a0, f2lo(w02), acc[e][4]);
                acc[e][5] = ffma2(a0, f2hi(w02), acc[e][5]);
                acc[e][6] = ffma2(a0, f2lo(w03), acc[e][6]);
                acc[e][7] = ffma2(a0, f2hi(w03), acc[e][7]);
                acc[e][0] = ffma2(a1, f2lo(w10), acc[e][0]);
                acc[e][1] = ffma2(a1, f2hi(w10), acc[e][1]);
                acc[e][2] = ffma2(a1, f2lo(w11), acc[e][2]);
                acc[e][3] = ffma2(a1, f2hi(w11), acc[e][3]);
                acc[e][4] = ffma2(a1, f2lo(w12), acc[e][4]);
                acc[e][5] = ffma2(a1, f2hi(w12), acc[e][5]);
                acc[e][6] = ffma2(a1, f2lo(w13), acc[e][6]);
                acc[e][7] = ffma2(a1, f2hi(w13), acc[e][7]);
            }
        }
    }

#pragma unroll
    for (int e = 0; e < 4; e++) {
        float2* Er = reinterpret_cast<float2*>(
                         g_EW1 + (size_t)(eBase + eg * 4 + e) * H) + hg * 8;
#pragma unroll
        for (int j = 0; j < 8; j++) Er[j] = acc[e][j];
    }
}

// ---------------------------------------------------------------------------
// Kernel 2: A[q,:] = s_emb[q]@W2 + r_emb[q]@W3 + b  (rows 256..767 of W).
// 128 threads; 8 queries/block (256 blocks). Thread = (qg=tid>>4, hg=tid&15).
// ---------------------------------------------------------------------------
__global__ void __launch_bounds__(128, 4)
aq_kernel(const int* __restrict__ s, const int* __restrict__ r,
          const float* __restrict__ ent, const float* __restrict__ rel,
          const float* __restrict__ W, const float* __restrict__ b) {
    __shared__ float2 sA[8 * 512];                    // 32 KB, duplicated
    __shared__ int sq[8], rq[8];
    const int tid   = threadIdx.x;
    const int hg    = tid & 15;
    const int qg    = tid >> 4;
    const int qBase = blockIdx.x * 8;

    if (tid < 8) { sq[tid] = s[qBase + tid]; rq[tid] = r[qBase + tid]; }
    __syncthreads();

    for (int idx = tid; idx < 8 * 512; idx += 128) {
        const int q = idx >> 9;
        const int k = idx & 511;
        const float v = (k < H) ? ent[(size_t)sq[q] * H + k]
                                : rel[(size_t)rq[q] * H + (k - H)];
        sA[idx] = make_float2(v, v);
    }
    __syncthreads();

    float2 acc[8];
    const float2* b2 = reinterpret_cast<const float2*>(b) + hg * 8;
#pragma unroll
    for (int j = 0; j < 8; j++) acc[j] = b2[j];

#pragma unroll 2
    for (int k = 0; k < 512; k += 2) {
        const float4* wr = reinterpret_cast<const float4*>(
                               W + (size_t)(H + k) * H) + (hg << 2);
        const float4 w00 = wr[0],  w01 = wr[1],  w02 = wr[2],  w03 = wr[3];
        const float4 w10 = wr[64], w11 = wr[65], w12 = wr[66], w13 = wr[67];
        const float4 ap = reinterpret_cast<const float4*>(sA)
                              [(qg << 8) + (k >> 1)];
        const float2 a0 = make_float2(ap.x, ap.y);
        const float2 a1 = make_float2(ap.z, ap.w);
        acc[0] = ffma2(a0, f2lo(w00), acc[0]);
        acc[1] = ffma2(a0, f2hi(w00), acc[1]);
        acc[2] = ffma2(a0, f2lo(w01), acc[2]);
        acc[3] = ffma2(a0, f2hi(w01), acc[3]);
        acc[4] = ffma2(a0, f2lo(w02), acc[4]);
        acc[5] = ffma2(a0, f2hi(w02), acc[5]);
        acc[6] = ffma2(a0, f2lo(w03), acc[6]);
        acc[7] = ffma2(a0, f2hi(w03), acc[7]);
        acc[0] = ffma2(a1, f2lo(w10), acc[0]);
        acc[1] = ffma2(a1, f2hi(w10), acc[1]);
        acc[2] = ffma2(a1, f2lo(w11), acc[2]);
        acc[3] = ffma2(a1, f2hi(w11), acc[3]);
        acc[4] = ffma2(a1, f2lo(w12), acc[4]);
        acc[5] = ffma2(a1, f2hi(w12), acc[5]);
        acc[6] = ffma2(a1, f2lo(w13), acc[6]);
        acc[7] = ffma2(a1, f2hi(w13), acc[7]);
    }

    float2* Ar = reinterpret_cast<float2*>(g_A + (size_t)(qBase + qg) * H) + hg * 8;
#pragma unroll
    for (int j = 0; j < 8; j++) Ar[j] = acc[j];
}

// ---------------------------------------------------------------------------
// Kernel 3: segment start offsets from sorted seg_ids.
// ---------------------------------------------------------------------------
__global__ void starts_kernel(const int* __restrict__ seg_ids) {
    const int i = blockIdx.x * blockDim.x + threadIdx.x;
    if (i >= NTOT) return;
    const int cur  = seg_ids[i];
    const int prev = (i == 0) ? -1 : seg_ids[i - 1];
    for (int sg = prev + 1; sg <= cur; sg++) g_starts[sg] = i;
    if (i == NTOT - 1)
        for (int sg = cur + 1; sg <= NSEG; sg++) g_starts[sg] = NTOT;
}

// ---------------------------------------------------------------------------
// Kernel 4: score = v . tanh(EW1[nbr] + A[q]).  Warp per neighbor.
// tanh via MUFU.TANH (tanh.approx.f32) — 1 instr instead of ~24.
// ---------------------------------------------------------------------------
__global__ void score_kernel(const int* __restrict__ nbr_ids,
                             const int* __restrict__ seg_ids,
                             const float* __restrict__ v) {
    const int warp = blockIdx.x * 8 + (threadIdx.x >> 5);
    const int lane = threadIdx.x & 31;
    if (warp >= NTOT) return;

    const int nbr = nbr_ids[warp];
    const int q   = seg_ids[warp] / SEQL;

    const float4* ew = reinterpret_cast<const float4*>(g_EW1 + (size_t)nbr * H);
    const float4* aq = reinterpret_cast<const float4*>(g_A + (size_t)q * H);
    const float4* vv = reinterpret_cast<const float4*>(v);

    float sum = 0.0f;
#pragma unroll
    for (int i = 0; i < 2; i++) {
        const int idx = lane + 32 * i;
        const float4 e4 = ew[idx];
        const float4 a4 = aq[idx];
        const float4 v4 = vv[idx];
        sum = fmaf(tanh_fast(e4.x + a4.x), v4.x, sum);
        sum = fmaf(tanh_fast(e4.y + a4.y), v4.y, sum);
        sum = fmaf(tanh_fast(e4.z + a4.z), v4.z, sum);
        sum = fmaf(tanh_fast(e4.w + a4.w), v4.w, sum);
    }
#pragma unroll
    for (int o = 16; o; o >>= 1) sum += __shfl_xor_sync(0xffffffffu, sum, o);
    if (lane == 0) g_scores[warp] = sum;
}

// ---------------------------------------------------------------------------
// Kernel 5: block per segment. Scores are bounded (|score| <= sum|v| ~ 10),
// so softmax needs NO max-subtraction: one exp-sum pass + weighted gather.
// ---------------------------------------------------------------------------
__global__ void agg_kernel(const int* __restrict__ s, const int* __restrict__ r,
                           const int* __restrict__ nbr_ids,
                           const float* __restrict__ ent, const float* __restrict__ rel,
                           float* __restrict__ out) {
    const int seg = blockIdx.x;
    const int tid = threadIdx.x;                      // 0..255, one per h
    const int lo  = g_starts[seg];
    const int hi  = g_starts[seg + 1];

    float* row = out + (size_t)seg * (3 * H);
    if (lo >= hi) {                                   // empty segment -> zeros
        row[tid] = 0.0f; row[H + tid] = 0.0f; row[2 * H + tid] = 0.0f;
        return;
    }
    const int q = seg / SEQL;

    __shared__ float red[8];
    __shared__ float wsm[256];
    __shared__ int   nsm[256];

    // single pass: sum of exp(score)
    float d = 0.0f;
    for (int j = lo + tid; j < hi; j += 256) d += __expf(g_scores[j]);
#pragma unroll
    for (int o = 16; o; o >>= 1) d += __shfl_xor_sync(0xffffffffu, d, o);
    if ((tid & 31) == 0) red[tid >> 5] = d;
    __syncthreads();
    float dsum = red[0];
#pragma unroll
    for (int w = 1; w < 8; w++) dsum += red[w];
    const float inv = 1.0f / dsum;

    // weighted aggregation of neighbor embeddings
    float a0 = 0.f, a1 = 0.f, a2 = 0.f, a3 = 0.f;
    for (int base = lo; base < hi; base += 256) {
        __syncthreads();
        const int j = base + tid;
        if (j < hi) {
            wsm[tid] = __expf(g_scores[j]) * inv;
            nsm[tid] = nbr_ids[j];
        }
        __syncthreads();
        const int cnt = min(hi - base, 256);
        int jj = 0;
        for (; jj + 4 <= cnt; jj += 4) {
            a0 = fmaf(wsm[jj + 0], ent[(size_t)nsm[jj + 0] * H + tid], a0);
            a1 = fmaf(wsm[jj + 1], ent[(size_t)nsm[jj + 1] * H + tid], a1);
            a2 = fmaf(wsm[jj + 2], ent[(size_t)nsm[jj + 2] * H + tid], a2);
            a3 = fmaf(wsm[jj + 3], ent[(size_t)nsm[jj + 3] * H + tid], a3);
        }
        for (; jj < cnt; jj++)
            a0 = fmaf(wsm[jj], ent[(size_t)nsm[jj] * H + tid], a0);
    }

    row[tid]         = (a0 + a1) + (a2 + a3);
    row[H + tid]     = ent[(size_t)s[q] * H + tid];
    row[2 * H + tid] = rel[(size_t)r[q] * H + tid];
}

// ---------------------------------------------------------------------------
extern "C" void kernel_launch(void* const* d_in, const int* in_sizes, int n_in,
                              void* d_out, int out_size) {
    const int*   s    = (const int*)d_in[0];
    const int*   r    = (const int*)d_in[1];
    const int*   nbr  = (const int*)d_in[2];
    const int*   segi = (const int*)d_in[3];
    const float* ent  = (const float*)d_in[4];
    const float* rel  = (const float*)d_in[5];
    const float* W    = (const float*)d_in[6];
    const float* b    = (const float*)d_in[7];
    const float* v    = (const float*)d_in[8];
    float* out = (float*)d_out;

    ew1_kernel<<<NENT / EW_EB, 128>>>(ent, W);
    aq_kernel<<<BQ / 8, 128>>>(s, r, ent, rel, W, b);
    starts_kernel<<<(NTOT + 255) / 256, 256>>>(segi);
    score_kernel<<<NTOT / 8, 256>>>(nbr, segi, v);
    agg_kernel<<<NSEG, 256>>>(s, r, nbr, ent, rel, out);
}

// round 3
// speedup vs baseline: 1.8144x; 1.8144x over previous
#include <cuda_runtime.h>

#define H     256
#define SEQL  10
#define BQ    2048
#define NTOT  327680
#define NSEG  (BQ * SEQL)  // 20480
#define NENT  20000

// ---------------- scratch (no cudaMalloc allowed) ----------------
__device__ float g_EW1[NENT * H];      // ent_embeds @ W1   (20.5 MB)
__device__ float g_A[BQ * H];          // s@W2 + r@W3 + b   (2 MB)
__device__ float g_scores[NTOT];       // per-neighbor attention score
__device__ int   g_starts[NSEG + 1];   // segment start offsets

// Packed fp32x2 FMA (Blackwell): two fp32 FMAs per instruction.
__device__ __forceinline__ float2 ffma2(float2 a, float2 b, float2 c) {
    float2 d;
    asm("fma.rn.f32x2 %0, %1, %2, %3;"
        : "=l"(reinterpret_cast<unsigned long long&>(d))
        : "l"(reinterpret_cast<const unsigned long long&>(a)),
          "l"(reinterpret_cast<const unsigned long long&>(b)),
          "l"(reinterpret_cast<const unsigned long long&>(c)));
    return d;
}

__device__ __forceinline__ float tanh_fast(float x) {
    float y;
    asm("tanh.approx.f32 %0, %1;" : "=f"(y) : "f"(x));
    return y;
}

__device__ __forceinline__ float2 f2lo(float4 v) { return make_float2(v.x, v.y); }
__device__ __forceinline__ float2 f2hi(float4 v) { return make_float2(v.z, v.w); }

// ===========================================================================
// Tiled GEMM core: C[BM=128 rows, BN=128 cols] += A[BM,K] * W[K, BN-slice].
// 256 threads: tm = tid>>4 (8 rows each), tn = tid&15.
// Thread's 8 cols are split: {tn*4..tn*4+3} and {64+tn*4..64+tn*4+3} so the
// sW LDS.128s are dense/conflict-free across the 16 tn lanes.
// sA holds duplicated float2 pairs so each FFMA2 gets dup(a_k) directly.
// ===========================================================================
#define BM 128
#define BN 128
#define BK 32

struct GemmAcc { float2 acc[8][4]; };

__device__ __forceinline__ void gemm_chunk(const float2* __restrict__ sA,   // [BK][BM]
                                           const float4* __restrict__ sW4,  // [BK][BN/4]
                                           int tm, int tn, GemmAcc& g) {
#pragma unroll 8
    for (int k = 0; k < BK; k++) {
        const float4* ar = reinterpret_cast<const float4*>(sA + k * BM + tm * 8);
        const float4 a01 = ar[0], a23 = ar[1], a45 = ar[2], a67 = ar[3];
        const float4 wA = sW4[k * (BN / 4) + tn];        // cols tn*4..+3
        const float4 wB = sW4[k * (BN / 4) + 16 + tn];   // cols 64+tn*4..+3
        const float2 w0 = f2lo(wA), w1 = f2hi(wA), w2 = f2lo(wB), w3 = f2hi(wB);
        float2 a[8] = { f2lo(a01), f2hi(a01), f2lo(a23), f2hi(a23),
                        f2lo(a45), f2hi(a45), f2lo(a67), f2hi(a67) };
#pragma unroll
        for (int e = 0; e < 8; e++) {
            g.acc[e][0] = ffma2(a[e], w0, g.acc[e][0]);
            g.acc[e][1] = ffma2(a[e], w1, g.acc[e][1]);
            g.acc[e][2] = ffma2(a[e], w2, g.acc[e][2]);
            g.acc[e][3] = ffma2(a[e], w3, g.acc[e][3]);
        }
    }
}

// ---------------------------------------------------------------------------
// Kernel 1: EW1 = ent_embeds @ W1 (rows 0..255 of W).  grid = (157, 2).
// ---------------------------------------------------------------------------
__global__ void __launch_bounds__(256)
ew1_kernel(const float* __restrict__ ent, const float* __restrict__ W) {
    __shared__ float2 sA[BK * BM];        // 32 KB (duplicated pairs, transposed)
    __shared__ float4 sW4[BK * (BN / 4)]; // 16 KB
    const int tid   = threadIdx.x;
    const int tm    = tid >> 4;
    const int tn    = tid & 15;
    const int eBase = blockIdx.x * BM;
    const int nBase = blockIdx.y * BN;

    GemmAcc g;
#pragma unroll
    for (int e = 0; e < 8; e++)
#pragma unroll
        for (int j = 0; j < 4; j++) g.acc[e][j] = make_float2(0.f, 0.f);

#pragma unroll 1
    for (int kc = 0; kc < H; kc += BK) {
        if (kc) __syncthreads();
        // stage A chunk: 128 ents x 32 k (transposed, duplicated)
#pragma unroll
        for (int i = 0; i < 4; i++) {
            const int idx = tid + 256 * i;
            const int e   = idx >> 3;
            const int kk  = (idx & 7) << 2;
            float4 v = make_float4(0.f, 0.f, 0.f, 0.f);
            if (eBase + e < NENT)
                v = *reinterpret_cast<const float4*>(
                        ent + (size_t)(eBase + e) * H + kc + kk);
            sA[(kk + 0) * BM + e] = make_float2(v.x, v.x);
            sA[(kk + 1) * BM + e] = make_float2(v.y, v.y);
            sA[(kk + 2) * BM + e] = make_float2(v.z, v.z);
            sA[(kk + 3) * BM + e] = make_float2(v.w, v.w);
        }
        // stage W chunk: 32 k x 128 cols
#pragma unroll
        for (int i = 0; i < 4; i++) {
            const int idx = tid + 256 * i;
            const int kk  = idx >> 5;
            const int c4  = idx & 31;
            sW4[kk * (BN / 4) + c4] = *(reinterpret_cast<const float4*>(
                W + (size_t)(kc + kk) * H + nBase) + c4);
        }
        __syncthreads();
        gemm_chunk(sA, sW4, tm, tn, g);
    }

#pragma unroll
    for (int e = 0; e < 8; e++) {
        const int ei = eBase + tm * 8 + e;
        if (ei < NENT) {
            float* row = g_EW1 + (size_t)ei * H + nBase;
            *reinterpret_cast<float4*>(row + tn * 4) =
                make_float4(g.acc[e][0].x, g.acc[e][0].y, g.acc[e][1].x, g.acc[e][1].y);
            *reinterpret_cast<float4*>(row + 64 + tn * 4) =
                make_float4(g.acc[e][2].x, g.acc[e][2].y, g.acc[e][3].x, g.acc[e][3].y);
        }
    }
}

// ---------------------------------------------------------------------------
// Kernel 2: A = [s_emb | r_emb] @ W[256:768] + b.  grid = (16, 2), K = 512.
// ---------------------------------------------------------------------------
__global__ void __launch_bounds__(256)
aq_kernel(const int* __restrict__ s, const int* __restrict__ r,
          const float* __restrict__ ent, const float* __restrict__ rel,
          const float* __restrict__ W, const float* __restrict__ b) {
    __shared__ float2 sA[BK * BM];
    __shared__ float4 sW4[BK * (BN / 4)];
    const int tid   = threadIdx.x;
    const int tm    = tid >> 4;
    const int tn    = tid & 15;
    const int qBase = blockIdx.x * BM;
    const int nBase = blockIdx.y * BN;

    GemmAcc g;
#pragma unroll
    for (int e = 0; e < 8; e++)
#pragma unroll
        for (int j = 0; j < 4; j++) g.acc[e][j] = make_float2(0.f, 0.f);

#pragma unroll 1
    for (int kc = 0; kc < 2 * H; kc += BK) {
        if (kc) __syncthreads();
#pragma unroll
        for (int i = 0; i < 4; i++) {
            const int idx = tid + 256 * i;
            const int q   = idx >> 3;
            const int kk  = (idx & 7) << 2;
            const float* src = (kc < H)
                ? ent + (size_t)s[qBase + q] * H + kc
                : rel + (size_t)r[qBase + q] * H + (kc - H);
            const float4 v = *reinterpret_cast<const float4*>(src + kk);
            sA[(kk + 0) * BM + q] = make_float2(v.x, v.x);
            sA[(kk + 1) * BM + q] = make_float2(v.y, v.y);
            sA[(kk + 2) * BM + q] = make_float2(v.z, v.z);
            sA[(kk + 3) * BM + q] = make_float2(v.w, v.w);
        }
#pragma unroll
        for (int i = 0; i < 4; i++) {
            const int idx = tid + 256 * i;
            const int kk  = idx >> 5;
            const int c4  = idx & 31;
            sW4[kk * (BN / 4) + c4] = *(reinterpret_cast<const float4*>(
                W + (size_t)(H + kc + kk) * H + nBase) + c4);
        }
        __syncthreads();
        gemm_chunk(sA, sW4, tm, tn, g);
    }

    // bias
    const float4 bA = *(reinterpret_cast<const float4*>(b + nBase) + tn);
    const float4 bB = *(reinterpret_cast<const float4*>(b + nBase + 64) + tn);
    const int q0 = qBase + tm * 8;
#pragma unroll
    for (int e = 0; e < 8; e++) {
        float* row = g_A + (size_t)(q0 + e) * H + nBase;
        *reinterpret_cast<float4*>(row + tn * 4) =
            make_float4(g.acc[e][0].x + bA.x, g.acc[e][0].y + bA.y,
                        g.acc[e][1].x + bA.z, g.acc[e][1].y + bA.w);
        *reinterpret_cast<float4*>(row + 64 + tn * 4) =
            make_float4(g.acc[e][2].x + bB.x, g.acc[e][2].y + bB.y,
                        g.acc[e][3].x + bB.z, g.acc[e][3].y + bB.w);
    }
}

// ---------------------------------------------------------------------------
// Kernel 3: segment start offsets from sorted seg_ids.
// ---------------------------------------------------------------------------
__global__ void starts_kernel(const int* __restrict__ seg_ids) {
    const int i = blockIdx.x * blockDim.x + threadIdx.x;
    if (i >= NTOT) return;
    const int cur  = seg_ids[i];
    const int prev = (i == 0) ? -1 : seg_ids[i - 1];
    for (int sg = prev + 1; sg <= cur; sg++) g_starts[sg] = i;
    if (i == NTOT - 1)
        for (int sg = cur + 1; sg <= NSEG; sg++) g_starts[sg] = NTOT;
}

// ---------------------------------------------------------------------------
// Kernel 4: scores, warp per SEGMENT. A[q] and v stay in registers across the
// segment's neighbors; per neighbor only the EW1 row is fetched (L2-resident).
// ---------------------------------------------------------------------------
__global__ void score_kernel(const int* __restrict__ nbr_ids,
                             const float* __restrict__ v) {
    const int seg  = blockIdx.x * 8 + (threadIdx.x >> 5);
    const int lane = threadIdx.x & 31;
    if (seg >= NSEG) return;
    const int lo = g_starts[seg];
    const int hi = g_starts[seg + 1];
    if (lo >= hi) return;
    const int q = seg / SEQL;

    const float4* aq = reinterpret_cast<const float4*>(g_A + (size_t)q * H);
    const float4* vv = reinterpret_cast<const float4*>(v);
    const float4 a0 = aq[lane], a1 = aq[lane + 32];
    const float4 v0 = vv[lane], v1 = vv[lane + 32];

    for (int j = lo; j < hi; j++) {
        const int nbr = nbr_ids[j];
        const float4* ew = reinterpret_cast<const float4*>(g_EW1 + (size_t)nbr * H);
        const float4 e0 = ew[lane], e1 = ew[lane + 32];
        float sum;
        sum = tanh_fast(e0.x + a0.x) * v0.x;
        sum = fmaf(tanh_fast(e0.y + a0.y), v0.y, sum);
        sum = fmaf(tanh_fast(e0.z + a0.z), v0.z, sum);
        sum = fmaf(tanh_fast(e0.w + a0.w), v0.w, sum);
        sum = fmaf(tanh_fast(e1.x + a1.x), v1.x, sum);
        sum = fmaf(tanh_fast(e1.y + a1.y), v1.y, sum);
        sum = fmaf(tanh_fast(e1.z + a1.z), v1.z, sum);
        sum = fmaf(tanh_fast(e1.w + a1.w), v1.w, sum);
#pragma unroll
        for (int o = 16; o; o >>= 1) sum += __shfl_xor_sync(0xffffffffu, sum, o);
        if (lane == 0) g_scores[j] = sum;
    }
}

// ---------------------------------------------------------------------------
// Kernel 5: block per segment. Scores bounded (|score| <= sum|v| ~ 10) so
// softmax needs no max pass: one exp-sum + weighted gather.
// ---------------------------------------------------------------------------
__global__ void agg_kernel(const int* __restrict__ s, const int* __restrict__ r,
                           const int* __restrict__ nbr_ids,
                           const float* __restrict__ ent, const float* __restrict__ rel,
                           float* __restrict__ out) {
    const int seg = blockIdx.x;
    const int tid = threadIdx.x;                      // 0..255, one per h
    const int lo  = g_starts[seg];
    const int hi  = g_starts[seg + 1];

    float* row = out + (size_t)seg * (3 * H);
    if (lo >= hi) {
        row[tid] = 0.0f; row[H + tid] = 0.0f; row[2 * H + tid] = 0.0f;
        return;
    }
    const int q = seg / SEQL;

    __shared__ float red[8];
    __shared__ float wsm[256];
    __shared__ int   nsm[256];

    float d = 0.0f;
    for (int j = lo + tid; j < hi; j += 256) d += __expf(g_scores[j]);
#pragma unroll
    for (int o = 16; o; o >>= 1) d += __shfl_xor_sync(0xffffffffu, d, o);
    if ((tid & 31) == 0) red[tid >> 5] = d;
    __syncthreads();
    float dsum = red[0];
#pragma unroll
    for (int w = 1; w < 8; w++) dsum += red[w];
    const float inv = 1.0f / dsum;

    float a0 = 0.f, a1 = 0.f, a2 = 0.f, a3 = 0.f;
    for (int base = lo; base < hi; base += 256) {
        __syncthreads();
        const int j = base + tid;
        if (j < hi) {
            wsm[tid] = __expf(g_scores[j]) * inv;
            nsm[tid] = nbr_ids[j];
        }
        __syncthreads();
        const int cnt = min(hi - base, 256);
        int jj = 0;
        for (; jj + 4 <= cnt; jj += 4) {
            a0 = fmaf(wsm[jj + 0], ent[(size_t)nsm[jj + 0] * H + tid], a0);
            a1 = fmaf(wsm[jj + 1], ent[(size_t)nsm[jj + 1] * H + tid], a1);
            a2 = fmaf(wsm[jj + 2], ent[(size_t)nsm[jj + 2] * H + tid], a2);
            a3 = fmaf(wsm[jj + 3], ent[(size_t)nsm[jj + 3] * H + tid], a3);
        }
        for (; jj < cnt; jj++)
            a0 = fmaf(wsm[jj], ent[(size_t)nsm[jj] * H + tid], a0);
    }

    row[tid]         = (a0 + a1) + (a2 + a3);
    row[H + tid]     = ent[(size_t)s[q] * H + tid];
    row[2 * H + tid] = rel[(size_t)r[q] * H + tid];
}

// ---------------------------------------------------------------------------
extern "C" void kernel_launch(void* const* d_in, const int* in_sizes, int n_in,
                              void* d_out, int out_size) {
    const int*   s    = (const int*)d_in[0];
    const int*   r    = (const int*)d_in[1];
    const int*   nbr  = (const int*)d_in[2];
    const int*   segi = (const int*)d_in[3];
    const float* ent  = (const float*)d_in[4];
    const float* rel  = (const float*)d_in[5];
    const float* W    = (const float*)d_in[6];
    const float* b    = (const float*)d_in[7];
    const float* v    = (const float*)d_in[8];
    float* out = (float*)d_out;

    starts_kernel<<<(NTOT + 255) / 256, 256>>>(segi);
    ew1_kernel<<<dim3((NENT + BM - 1) / BM, H / BN), 256>>>(ent, W);
    aq_kernel<<<dim3(BQ / BM, H / BN), 256>>>(s, r, ent, rel, W, b);
    score_kernel<<<(NSEG + 7) / 8, 256>>>(nbr, v);
    agg_kernel<<<NSEG, 256>>>(s, r, nbr, ent, rel, out);
}

// round 5
// speedup vs baseline: 2.0848x; 1.1490x over previous
#include <cuda_runtime.h>

#define H     256
#define SEQL  10
#define BQ    2048
#define NTOT  327680
#define NSEG  (BQ * SEQL)  // 20480
#define NENT  20000

// ---------------- scratch (no cudaMalloc allowed) ----------------
__device__ float g_EW1[NENT * H];      // ent_embeds @ W1   (20.5 MB)
__device__ float g_A[BQ * H];          // s@W2 + r@W3 + b   (2 MB)
__device__ float g_scores[NTOT];       // exp(score) per neighbor
__device__ float g_dsum[NSEG];         // per-segment sum of exp(score)
__device__ int   g_starts[NSEG + 1];   // segment start offsets

// Packed fp32x2 FMA (Blackwell): two fp32 FMAs per instruction.
__device__ __forceinline__ float2 ffma2(float2 a, float2 b, float2 c) {
    float2 d;
    asm("fma.rn.f32x2 %0, %1, %2, %3;"
        : "=l"(reinterpret_cast<unsigned long long&>(d))
        : "l"(reinterpret_cast<const unsigned long long&>(a)),
          "l"(reinterpret_cast<const unsigned long long&>(b)),
          "l"(reinterpret_cast<const unsigned long long&>(c)));
    return d;
}

__device__ __forceinline__ float tanh_fast(float x) {
    float y;
    asm("tanh.approx.f32 %0, %1;" : "=f"(y) : "f"(x));
    return y;
}

__device__ __forceinline__ float2 f2lo(float4 v) { return make_float2(v.x, v.y); }
__device__ __forceinline__ float2 f2hi(float4 v) { return make_float2(v.z, v.w); }

// ===========================================================================
// Kernel 1: EW1 = ent_embeds @ W1 (rows 0..255 of W).
// BM=128 x BN=128 x BK=16, 256 threads. tm=tid>>4 (8 rows), tn=tid&15.
// sA rows hold dup-pair float4s {ak,ak,ak+1,ak+1}; row stride 9 float4
// (8 + 1 pad): staging STS.128 and compute LDS both conflict-free.
// Static smem = 18 KB + 8 KB = 26.6 KB (< 48 KB limit).
// ===========================================================================
#define BM 128
#define BN 128
#define BK 16
#define SAW (BK / 2 + 1)   // 9 float4 per sA row

__global__ void __launch_bounds__(256)
ew1_kernel(const float* __restrict__ ent, const float* __restrict__ W) {
    __shared__ float4 sA[BM * SAW];       // 18 KB
    __shared__ float4 sW[BK * (BN / 4)];  // 8 KB
    const int tid   = threadIdx.x;
    const int tm    = tid >> 4;
    const int tn    = tid & 15;
    const int eBase = blockIdx.x * BM;
    const int nBase = blockIdx.y * BN;

    float2 acc[8][4];
#pragma unroll
    for (int e = 0; e < 8; e++)
#pragma unroll
        for (int j = 0; j < 4; j++) acc[e][j] = make_float2(0.f, 0.f);

#pragma unroll 1
    for (int kc = 0; kc < H; kc += BK) {
        if (kc) __syncthreads();
        // stage A: 128 rows x 16 k = 512 global float4 -> 2 per thread
#pragma unroll
        for (int i = 0; i < 2; i++) {
            const int idx = tid + 256 * i;
            const int e   = idx >> 2;
            const int k4  = idx & 3;
            float4 v = make_float4(0.f, 0.f, 0.f, 0.f);
            if (eBase + e < NENT)
                v = *reinterpret_cast<const float4*>(
                        ent + (size_t)(eBase + e) * H + kc + k4 * 4);
            sA[e * SAW + k4 * 2 + 0] = make_float4(v.x, v.x, v.y, v.y);
            sA[e * SAW + k4 * 2 + 1] = make_float4(v.z, v.z, v.w, v.w);
        }
        // stage W: 16 k-rows x 128 cols = 512 float4 -> 2 per thread
#pragma unroll
        for (int i = 0; i < 2; i++) {
            const int idx = tid + 256 * i;
            const int kk  = idx >> 5;
            const int c4  = idx & 31;
            sW[kk * (BN / 4) + c4] = *(reinterpret_cast<const float4*>(
                W + (size_t)(kc + kk) * H + nBase) + c4);
        }
        __syncthreads();

#pragma unroll
        for (int k2 = 0; k2 < BK / 2; k2++) {
            const float4 wA0 = sW[(2 * k2) * (BN / 4) + tn];
            const float4 wB0 = sW[(2 * k2) * (BN / 4) + 16 + tn];
            const float4 wA1 = sW[(2 * k2 + 1) * (BN / 4) + tn];
            const float4 wB1 = sW[(2 * k2 + 1) * (BN / 4) + 16 + tn];
#pragma unroll
            for (int e = 0; e < 8; e++) {
                const float4 a = sA[(tm * 8 + e) * SAW + k2];  // {ak,ak,ak1,ak1}
                const float2 a0 = f2lo(a), a1 = f2hi(a);
                acc[e][0] = ffma2(a0, f2lo(wA0), acc[e][0]);
                acc[e][1] = ffma2(a0, f2hi(wA0), acc[e][1]);
                acc[e][2] = ffma2(a0, f2lo(wB0), acc[e][2]);
                acc[e][3] = ffma2(a0, f2hi(wB0), acc[e][3]);
                acc[e][0] = ffma2(a1, f2lo(wA1), acc[e][0]);
                acc[e][1] = ffma2(a1, f2hi(wA1), acc[e][1]);
                acc[e][2] = ffma2(a1, f2lo(wB1), acc[e][2]);
                acc[e][3] = ffma2(a1, f2hi(wB1), acc[e][3]);
            }
        }
    }

#pragma unroll
    for (int e = 0; e < 8; e++) {
        const int ei = eBase + tm * 8 + e;
        if (ei < NENT) {
            float* row = g_EW1 + (size_t)ei * H + nBase;
            *reinterpret_cast<float4*>(row + tn * 4) =
                make_float4(acc[e][0].x, acc[e][0].y, acc[e][1].x, acc[e][1].y);
            *reinterpret_cast<float4*>(row + 64 + tn * 4) =
                make_float4(acc[e][2].x, acc[e][2].y, acc[e][3].x, acc[e][3].y);
        }
    }
}

// ===========================================================================
// Kernel 2: A = [s_emb | r_emb] @ W[256:768] + b.  64x64 tiles -> 128 blocks.
// 256 threads: tm=tid>>4 (4 rows), tn=tid&15 (4 cols). K = 512, BK=16.
// ===========================================================================
#define QBM 64
#define QBN 64
__global__ void __launch_bounds__(256)
aq_kernel(const int* __restrict__ s, const int* __restrict__ r,
          const float* __restrict__ ent, const float* __restrict__ rel,
          const float* __restrict__ W, const float* __restrict__ b) {
    __shared__ float4 sA[QBM * SAW];       // 9 KB
    __shared__ float4 sW[BK * (QBN / 4)];  // 4 KB
    __shared__ int sidx[QBM], ridx[QBM];
    const int tid   = threadIdx.x;
    const int tm    = tid >> 4;
    const int tn    = tid & 15;
    const int qBase = blockIdx.x * QBM;
    const int nBase = blockIdx.y * QBN;

    if (tid < QBM) { sidx[tid] = s[qBase + tid]; ridx[tid] = r[qBase + tid]; }
    __syncthreads();

    float2 acc[4][2];
#pragma unroll
    for (int e = 0; e < 4; e++) {
        acc[e][0] = make_float2(0.f, 0.f);
        acc[e][1] = make_float2(0.f, 0.f);
    }

#pragma unroll 1
    for (int kc = 0; kc < 2 * H; kc += BK) {
        __syncthreads();
        // stage A: 64 rows x 16 k = 256 global float4 -> 1 per thread
        {
            const int e  = tid >> 2;
            const int k4 = tid & 3;
            const float* src = (kc < H)
                ? ent + (size_t)sidx[e] * H + kc
                : rel + (size_t)ridx[e] * H + (kc - H);
            const float4 v = *reinterpret_cast<const float4*>(src + k4 * 4);
            sA[e * SAW + k4 * 2 + 0] = make_float4(v.x, v.x, v.y, v.y);
            sA[e * SAW + k4 * 2 + 1] = make_float4(v.z, v.z, v.w, v.w);
        }
        // stage W: 16 k-rows x 64 cols = 256 float4 -> 1 per thread
        {
            const int kk = tid >> 4;
            const int c4 = tid & 15;
            sW[kk * (QBN / 4) + c4] = *(reinterpret_cast<const float4*>(
                W + (size_t)(H + kc + kk) * H + nBase) + c4);
        }
        __syncthreads();

#pragma unroll
        for (int k2 = 0; k2 < BK / 2; k2++) {
            const float4 w0 = sW[(2 * k2) * (QBN / 4) + tn];
            const float4 w1 = sW[(2 * k2 + 1) * (QBN / 4) + tn];
#pragma unroll
            for (int e = 0; e < 4; e++) {
                const float4 a = sA[(tm * 4 + e) * SAW + k2];
                acc[e][0] = ffma2(f2lo(a), f2lo(w0), acc[e][0]);
                acc[e][1] = ffma2(f2lo(a), f2hi(w0), acc[e][1]);
                acc[e][0] = ffma2(f2hi(a), f2lo(w1), acc[e][0]);
                acc[e][1] = ffma2(f2hi(a), f2hi(w1), acc[e][1]);
            }
        }
    }

    const float4 b4 = *reinterpret_cast<const float4*>(b + nBase + tn * 4);
#pragma unroll
    for (int e = 0; e < 4; e++) {
        float* row = g_A + (size_t)(qBase + tm * 4 + e) * H + nBase;
        *reinterpret_cast<float4*>(row + tn * 4) =
            make_float4(acc[e][0].x + b4.x, acc[e][0].y + b4.y,
                        acc[e][1].x + b4.z, acc[e][1].y + b4.w);
    }
}

// ---------------------------------------------------------------------------
// Kernel 3: segment start offsets from sorted seg_ids.
// ---------------------------------------------------------------------------
__global__ void starts_kernel(const int* __restrict__ seg_ids) {
    const int i = blockIdx.x * blockDim.x + threadIdx.x;
    if (i >= NTOT) return;
    const int cur  = seg_ids[i];
    const int prev = (i == 0) ? -1 : seg_ids[i - 1];
    for (int sg = prev + 1; sg <= cur; sg++) g_starts[sg] = i;
    if (i == NTOT - 1)
        for (int sg = cur + 1; sg <= NSEG; sg++) g_starts[sg] = NTOT;
}

// ---------------------------------------------------------------------------
// Kernel 4: warp per segment, 4 neighbors per iteration for ILP.
// Stores exp(score) into g_scores and the segment exp-sum into g_dsum.
// (|score| <= sum|v| ~ 10 so exp without max-subtraction is safe in fp32.)
// ---------------------------------------------------------------------------
__global__ void score_kernel(const int* __restrict__ nbr_ids,
                             const float* __restrict__ v) {
    const int seg  = blockIdx.x * 8 + (threadIdx.x >> 5);
    const int lane = threadIdx.x & 31;
    if (seg >= NSEG) return;
    const int lo = g_starts[seg];
    const int hi = g_starts[seg + 1];
    if (lo >= hi) return;
    const int q = seg / SEQL;

    const float4* aq = reinterpret_cast<const float4*>(g_A + (size_t)q * H);
    const float4* vv = reinterpret_cast<const float4*>(v);
    const float4 a0 = aq[lane], a1 = aq[lane + 32];
    const float4 v0 = vv[lane], v1 = vv[lane + 32];

    float dsum = 0.0f;
    for (int j0 = lo; j0 < hi; j0 += 4) {
        int n[4];
#pragma unroll
        for (int t = 0; t < 4; t++)
            n[t] = nbr_ids[min(j0 + t, hi - 1)];

        float sum[4];
#pragma unroll
        for (int t = 0; t < 4; t++) {
            const float4* ew = reinterpret_cast<const float4*>(
                                   g_EW1 + (size_t)n[t] * H);
            const float4 e0 = ew[lane], e1 = ew[lane + 32];
            float sc;
            sc = tanh_fast(e0.x + a0.x) * v0.x;
            sc = fmaf(tanh_fast(e0.y + a0.y), v0.y, sc);
            sc = fmaf(tanh_fast(e0.z + a0.z), v0.z, sc);
            sc = fmaf(tanh_fast(e0.w + a0.w), v0.w, sc);
            sc = fmaf(tanh_fast(e1.x + a1.x), v1.x, sc);
            sc = fmaf(tanh_fast(e1.y + a1.y), v1.y, sc);
            sc = fmaf(tanh_fast(e1.z + a1.z), v1.z, sc);
            sc = fmaf(tanh_fast(e1.w + a1.w), v1.w, sc);
            sum[t] = sc;
        }
        // 4 independent butterfly trees (pipelined)
#pragma unroll
        for (int o = 16; o; o >>= 1) {
#pragma unroll
            for (int t = 0; t < 4; t++)
                sum[t] += __shfl_xor_sync(0xffffffffu, sum[t], o);
        }
#pragma unroll
        for (int t = 0; t < 4; t++) {
            if (j0 + t < hi) {
                const float e = __expf(sum[t]);
                dsum += e;
                if (lane == 0) g_scores[j0 + t] = e;
            }
        }
    }
    if (lane == 0) g_dsum[seg] = dsum;
}

// ---------------------------------------------------------------------------
// Kernel 5: block per segment; weights come precomputed (exp / dsum).
// Single pass: stage (w, nbr) in smem, gather-accumulate, assemble output.
// ---------------------------------------------------------------------------
__global__ void agg_kernel(const int* __restrict__ s, const int* __restrict__ r,
                           const int* __restrict__ nbr_ids,
                           const float* __restrict__ ent, const float* __restrict__ rel,
                           float* __restrict__ out) {
    const int seg = blockIdx.x;
    const int tid = threadIdx.x;                      // 0..255, one per h
    const int lo  = g_starts[seg];
    const int hi  = g_starts[seg + 1];

    float* row = out + (size_t)seg * (3 * H);
    if (lo >= hi) {
        row[tid] = 0.0f; row[H + tid] = 0.0f; row[2 * H + tid] = 0.0f;
        return;
    }
    const int q   = seg / SEQL;
    const float inv = 1.0f / g_dsum[seg];

    __shared__ float wsm[256];
    __shared__ int   nsm[256];

    float a0 = 0.f, a1 = 0.f, a2 = 0.f, a3 = 0.f;
    for (int base = lo; base < hi; base += 256) {
        if (base != lo) __syncthreads();
        const int j = base + tid;
        if (j < hi) {
            wsm[tid] = g_scores[j] * inv;
            nsm[tid] = nbr_ids[j];
        }
        __syncthreads();
        const int cnt = min(hi - base, 256);
        int jj = 0;
        for (; jj + 4 <= cnt; jj += 4) {
            a0 = fmaf(wsm[jj + 0], ent[(size_t)nsm[jj + 0] * H + tid], a0);
            a1 = fmaf(wsm[jj + 1], ent[(size_t)nsm[jj + 1] * H + tid], a1);
            a2 = fmaf(wsm[jj + 2], ent[(size_t)nsm[jj + 2] * H + tid], a2);
            a3 = fmaf(wsm[jj + 3], ent[(size_t)nsm[jj + 3] * H + tid], a3);
        }
        for (; jj < cnt; jj++)
            a0 = fmaf(wsm[jj], ent[(size_t)nsm[jj] * H + tid], a0);
    }

    row[tid]         = (a0 + a1) + (a2 + a3);
    row[H + tid]     = ent[(size_t)s[q] * H + tid];
    row[2 * H + tid] = rel[(size_t)r[q] * H + tid];
}

// ---------------------------------------------------------------------------
extern "C" void kernel_launch(void* const* d_in, const int* in_sizes, int n_in,
                              void* d_out, int out_size) {
    const int*   s    = (const int*)d_in[0];
    const int*   r    = (const int*)d_in[1];
    const int*   nbr  = (const int*)d_in[2];
    const int*   segi = (const int*)d_in[3];
    const float* ent  = (const float*)d_in[4];
    const float* rel  = (const float*)d_in[5];
    const float* W    = (const float*)d_in[6];
    const float* b    = (const float*)d_in[7];
    const float* v    = (const float*)d_in[8];
    float* out = (float*)d_out;

    starts_kernel<<<(NTOT + 255) / 256, 256>>>(segi);
    ew1_kernel<<<dim3((NENT + BM - 1) / BM, H / BN), 256>>>(ent, W);
    aq_kernel<<<dim3(BQ / QBM, H / QBN), 256>>>(s, r, ent, rel, W, b);
    score_kernel<<<(NSEG + 7) / 8, 256>>>(nbr, v);
    agg_kernel<<<NSEG, 256>>>(s, r, nbr, ent, rel, out);
}